// round 3
// baseline (speedup 1.0000x reference)
#include <cuda_runtime.h>
#include <cuda_fp16.h>
#include <cstdint>

#define VOCAB 32000
#define HID   128
#define BATCH 4
#define SEQT  2048
#define BT    (BATCH*SEQT)

// ---------------- scratch (static device globals; no runtime allocation) ----------------
__device__ __align__(16) float g_c0[BT*HID];        // layer0 input proj + biases
__device__ __align__(16) float g_c1[BT*HID];        // layer1 input proj + biases
__device__ __align__(16) float g_y0[BT*HID];        // layer0 outputs (fp32, feeds proj1)
__device__ __align__(16) __half g_yhi[BT*HID];      // layer1 outputs split hi (fp16)
__device__ __align__(16) __half g_ylo[BT*HID];      // layer1 outputs split lo
__device__ __align__(16) __half g_whi[VOCAB*HID];   // fc_w split hi
__device__ __align__(16) __half g_wlo[VOCAB*HID];   // fc_w split lo
__device__ int g_is64;

// ---------------- dtype probe: is x int64 or int32? ----------------
__global__ void detect_kernel(const int* x32) {
    if (threadIdx.x == 0) {
        int acc = 0;
        #pragma unroll
        for (int i = 0; i < 64; i++) acc |= x32[2*i + 1];
        g_is64 = (acc == 0) ? 1 : 0;
    }
}

// ---------------- fc_w -> fp16 split ----------------
__global__ void wsplit_kernel(const float* __restrict__ w) {
    int i = blockIdx.x * blockDim.x + threadIdx.x;
    if (i < VOCAB*HID) {
        float v = w[i];
        __half hi = __float2half_rn(v);
        g_whi[i] = hi;
        g_wlo[i] = __float2half_rn(v - __half2float(hi));
    }
}

// ---------------- input projection ----------------
__global__ __launch_bounds__(128) void proj_kernel(
    const void* __restrict__ xin, const float* __restrict__ emb,
    const float* __restrict__ W, const float* __restrict__ ba,
    const float* __restrict__ bb, int layer)
{
    __shared__ float sx[32][HID];
    const int j = threadIdx.x;
    const int chunk = blockIdx.x;

    float w[HID];
    #pragma unroll
    for (int k = 0; k < HID; k += 4) {
        float4 v = *(const float4*)(W + j*HID + k);
        w[k] = v.x; w[k+1] = v.y; w[k+2] = v.z; w[k+3] = v.w;
    }

    if (layer == 0) {
        const int is64 = g_is64;
        for (int r = 0; r < 32; r++) {
            int bt = chunk*32 + r;
            long long idx = is64 ? ((const long long*)xin)[bt]
                                 : (long long)((const int*)xin)[bt];
            sx[r][j] = emb[idx*HID + j];
        }
    } else {
        for (int r = 0; r < 32; r++) {
            int bt = chunk*32 + r;
            sx[r][j] = g_y0[bt*HID + j];
        }
    }
    __syncthreads();

    const float bias = ba[j] + bb[j];
    float* outc = (layer == 0) ? g_c0 : g_c1;
    for (int r = 0; r < 32; r++) {
        float acc = bias;
        #pragma unroll
        for (int k = 0; k < HID; k++) acc += w[k] * sx[r][k];
        outc[(chunk*32 + r)*HID + j] = acc;
    }
}

// ---------------- recurrent chain: one CTA per batch ----------------
typedef unsigned long long ull;
__global__ __launch_bounds__(128, 1) void chain_kernel(
    const float* __restrict__ Whh, const float* __restrict__ h0,
    float* __restrict__ hout, int layer)
{
    __shared__ float sh[2][HID];
    const int b = blockIdx.x;
    const int j = threadIdx.x;

    ull w2[HID/2];
    #pragma unroll
    for (int k = 0; k < HID/2; k++)
        w2[k] = ((const ull*)(Whh + j*HID))[k];

    sh[0][j] = h0[b*HID + j];
    __syncthreads();

    const float* cb = (layer == 0 ? g_c0 : g_c1) + (size_t)b*SEQT*HID;
    float cnext = cb[j];

    for (int t = 0; t < SEQT; t++) {
        const float cc = cnext;
        if (t + 1 < SEQT) cnext = __ldg(&cb[(size_t)(t+1)*HID + j]);

        const ull* hb = (const ull*)sh[t & 1];
        ull a0 = 0ull, a1 = 0ull, a2 = 0ull, a3 = 0ull;   // 4 indep packed chains
        #pragma unroll
        for (int k = 0; k < 16; k++) {
            asm("fma.rn.f32x2 %0, %1, %2, %0;" : "+l"(a0) : "l"(w2[k]),    "l"(hb[k]));
            asm("fma.rn.f32x2 %0, %1, %2, %0;" : "+l"(a1) : "l"(w2[k+16]), "l"(hb[k+16]));
            asm("fma.rn.f32x2 %0, %1, %2, %0;" : "+l"(a2) : "l"(w2[k+32]), "l"(hb[k+32]));
            asm("fma.rn.f32x2 %0, %1, %2, %0;" : "+l"(a3) : "l"(w2[k+48]), "l"(hb[k+48]));
        }
        float s = cc
            + __uint_as_float((unsigned)a0) + __uint_as_float((unsigned)(a0 >> 32))
            + __uint_as_float((unsigned)a1) + __uint_as_float((unsigned)(a1 >> 32))
            + __uint_as_float((unsigned)a2) + __uint_as_float((unsigned)(a2 >> 32))
            + __uint_as_float((unsigned)a3) + __uint_as_float((unsigned)(a3 >> 32));
        float hn = tanhf(s);

        sh[(t + 1) & 1][j] = hn;
        int bt = b*SEQT + t;
        if (layer == 0) {
            g_y0[bt*HID + j] = hn;
        } else {
            __half hi = __float2half_rn(hn);
            g_yhi[bt*HID + j] = hi;
            g_ylo[bt*HID + j] = __float2half_rn(hn - __half2float(hi));
        }
        __syncthreads();
    }
    hout[b*HID + j] = sh[SEQT & 1][j];
}

// ---------------- fc GEMM: split-fp16 mma.sync, tile 128x256, whole K resident ----------------
#define BM 128
#define BN 256
#define ROWB 272                    // padded row stride in bytes (136 fp16): conflict-free ldmatrix
#define A_TILE (128*ROWB)           // 34816
#define B_TILE (256*ROWB)           // 69632
#define OFF_BIAS 0
#define OFF_A 1024
#define OFF_B (OFF_A + 2*A_TILE)    // 70656
#define FC_SMEM (OFF_B + 2*B_TILE)  // 209920

__device__ __forceinline__ void ldsm_x4(uint32_t addr, uint32_t& r0, uint32_t& r1,
                                        uint32_t& r2, uint32_t& r3) {
    asm volatile("ldmatrix.sync.aligned.m8n8.x4.shared.b16 {%0,%1,%2,%3}, [%4];"
                 : "=r"(r0), "=r"(r1), "=r"(r2), "=r"(r3) : "r"(addr));
}
__device__ __forceinline__ void mma16816(float* c, uint32_t a0, uint32_t a1,
                                         uint32_t a2, uint32_t a3,
                                         uint32_t b0, uint32_t b1) {
    asm volatile("mma.sync.aligned.m16n8k16.row.col.f32.f16.f16.f32 "
        "{%0,%1,%2,%3}, {%4,%5,%6,%7}, {%8,%9}, {%0,%1,%2,%3};"
        : "+f"(c[0]), "+f"(c[1]), "+f"(c[2]), "+f"(c[3])
        : "r"(a0), "r"(a1), "r"(a2), "r"(a3), "r"(b0), "r"(b1));
}

__global__ __launch_bounds__(512) void fc_kernel(const float* __restrict__ fc_b,
                                                 float* __restrict__ out) {
    extern __shared__ char sm[];
    const int tid = threadIdx.x;
    const int n0 = blockIdx.x * BN;
    const int m0 = blockIdx.y * BM;

    if (tid < 256) ((float*)sm)[tid] = fc_b[n0 + tid];

    // fill tiles: rows of 128 fp16 = 16 x 16B chunks, padded to ROWB
    for (int i = tid; i < 128*16; i += 512) {
        int r = i >> 4, c = i & 15;
        *(uint4*)(sm + OFF_A + r*ROWB + c*16) =
            ((const uint4*)(g_yhi + (size_t)(m0+r)*HID))[c];
        *(uint4*)(sm + OFF_A + A_TILE + r*ROWB + c*16) =
            ((const uint4*)(g_ylo + (size_t)(m0+r)*HID))[c];
    }
    for (int i = tid; i < 256*16; i += 512) {
        int r = i >> 4, c = i & 15;
        *(uint4*)(sm + OFF_B + r*ROWB + c*16) =
            ((const uint4*)(g_whi + (size_t)(n0+r)*HID))[c];
        *(uint4*)(sm + OFF_B + B_TILE + r*ROWB + c*16) =
            ((const uint4*)(g_wlo + (size_t)(n0+r)*HID))[c];
    }
    __syncthreads();

    const int lane = tid & 31, wid = tid >> 5;
    const int wm = wid >> 2, wn = wid & 3;      // 4x4 warps, warp tile 32m x 64n
    const uint32_t smem_base = (uint32_t)__cvta_generic_to_shared(sm);

    // ldmatrix bases: row = lane&15, 16B col-group = lane>>4
    const uint32_t a_base = smem_base + OFF_A + (wm*32 + (lane & 15))*ROWB + (lane >> 4)*16;
    const uint32_t b_base = smem_base + OFF_B + (wn*64 + (lane & 15))*ROWB + (lane >> 4)*16;

    float acc[2][8][4];
    #pragma unroll
    for (int mi = 0; mi < 2; mi++)
        #pragma unroll
        for (int ni = 0; ni < 8; ni++)
            #pragma unroll
            for (int q = 0; q < 4; q++) acc[mi][ni][q] = 0.f;

    const int apass[3] = {0, 1, 0};   // hi, lo, hi
    const int bpass[3] = {0, 0, 1};   // hi, hi, lo

    #pragma unroll
    for (int p = 0; p < 3; p++) {
        const uint32_t ao = a_base + apass[p]*A_TILE;
        const uint32_t bo = b_base + bpass[p]*B_TILE;
        #pragma unroll
        for (int k0 = 0; k0 < 8; k0++) {
            const uint32_t kb = k0*32;   // 16 fp16 per k-step
            uint32_t a[2][4];
            ldsm_x4(ao + kb,            a[0][0], a[0][1], a[0][2], a[0][3]);
            ldsm_x4(ao + 16*ROWB + kb,  a[1][0], a[1][1], a[1][2], a[1][3]);
            uint32_t bfr[8][2];
            #pragma unroll
            for (int np = 0; np < 4; np++) {
                uint32_t r0, r1, r2, r3;
                ldsm_x4(bo + np*(16*ROWB) + kb, r0, r1, r2, r3);
                bfr[2*np][0]   = r0; bfr[2*np][1]   = r2;
                bfr[2*np+1][0] = r1; bfr[2*np+1][1] = r3;
            }
            #pragma unroll
            for (int mi = 0; mi < 2; mi++)
                #pragma unroll
                for (int ni = 0; ni < 8; ni++)
                    mma16816(acc[mi][ni], a[mi][0], a[mi][1], a[mi][2], a[mi][3],
                             bfr[ni][0], bfr[ni][1]);
        }
    }

    // epilogue: c0,c1 -> row lane/4, cols (lane%4)*2+{0,1}; c2,c3 -> row+8
    const float* bias = (const float*)sm;
    const int r_lo = m0 + wm*32 + (lane >> 2);
    #pragma unroll
    for (int mi = 0; mi < 2; mi++) {
        #pragma unroll
        for (int ni = 0; ni < 8; ni++) {
            const int col = wn*64 + ni*8 + (lane & 3)*2;
            const float b0 = bias[col], b1 = bias[col + 1];
            float2 v0 = make_float2(acc[mi][ni][0] + b0, acc[mi][ni][1] + b1);
            float2 v1 = make_float2(acc[mi][ni][2] + b0, acc[mi][ni][3] + b1);
            *(float2*)(out + (size_t)(r_lo + mi*16    )*VOCAB + n0 + col) = v0;
            *(float2*)(out + (size_t)(r_lo + mi*16 + 8)*VOCAB + n0 + col) = v1;
        }
    }
}

// ---------------- launch ----------------
extern "C" void kernel_launch(void* const* d_in, const int* in_sizes, int n_in,
                              void* d_out, int out_size) {
    const void*  x      = d_in[0];
    const float* hidden = (const float*)d_in[1];
    const float* emb    = (const float*)d_in[2];
    const float* W_ih0  = (const float*)d_in[3];
    const float* W_hh0  = (const float*)d_in[4];
    const float* b_ih0  = (const float*)d_in[5];
    const float* b_hh0  = (const float*)d_in[6];
    const float* W_ih1  = (const float*)d_in[7];
    const float* W_hh1  = (const float*)d_in[8];
    const float* b_ih1  = (const float*)d_in[9];
    const float* b_hh1  = (const float*)d_in[10];
    const float* fc_w   = (const float*)d_in[11];
    const float* fc_b   = (const float*)d_in[12];
    float* out = (float*)d_out;
    float* out_hidden = out + (size_t)BT * VOCAB;   // logits first, then [2,B,H]

    detect_kernel<<<1, 32>>>((const int*)x);
    wsplit_kernel<<<(VOCAB*HID + 255)/256, 256>>>(fc_w);
    proj_kernel<<<BT/32, 128>>>(x, emb, W_ih0, b_ih0, b_hh0, 0);
    chain_kernel<<<BATCH, 128>>>(W_hh0, hidden, out_hidden, 0);
    proj_kernel<<<BT/32, 128>>>(x, emb, W_ih1, b_ih1, b_hh1, 1);
    chain_kernel<<<BATCH, 128>>>(W_hh1, hidden + BATCH*HID, out_hidden + BATCH*HID, 1);

    cudaFuncSetAttribute(fc_kernel, cudaFuncAttributeMaxDynamicSharedMemorySize, FC_SMEM);
    fc_kernel<<<dim3(VOCAB/BN, BT/BM), 512, FC_SMEM>>>(fc_b, out);
}